// round 1
// baseline (speedup 1.0000x reference)
#include <cuda_runtime.h>
#include <math.h>

#define IMG_H 2048
#define IMG_W 2048
#define NIMG  4
#define NPIX  (IMG_H * IMG_W)      /* 4194304 */
#define OUTHW 2038                 /* 2048 - 11 + 1 */

#define C1V 6.5025f
#define C2V 58.5225f

// Gaussian(11, sigma=1.5) taps, normalized (computed in f64, rounded to f32).
#define GW0 0.00102838f
#define GW1 0.00759876f
#define GW2 0.03600077f
#define GW3 0.10936068f
#define GW4 0.21300553f
#define GW5 0.26601172f

__device__ __constant__ float c_unused = 0.f; // keep nvcc happy about empty const seg

// scratch accumulators (doubles):
// 0 l1, 1 gx, 2 gy, 3 range, 4..7 sum_p[b], 8..11 sum_t[b],
// 12..15 sumsq_p[b], 16..19 sumsq_t[b], 20..23 mse8[b], 32..47 ssim partials
__device__ double g_acc[64];

__device__ __forceinline__ float quant_u8(float x) {
    // identical f32 op sequence to the reference _to_uint8_float
    x = fminf(fmaxf(x, -1.0f), 1.0f);
    float x01 = (x + 1.0f) * 0.5f;
    x01 = fminf(fmaxf(x01, 0.0f), 1.0f);
    float v = x01 * 255.0f;
    v = fminf(v, 255.0f);
    return floorf(v);
}

__global__ void zero_kernel() {
    g_acc[threadIdx.x] = 0.0;
}

// ---------------------------------------------------------------------------
// Stats kernel: L1, grad (gx along H, gy along W), range penalty, per-image
// sums / sums-of-squares, per-image quantized MSE. Row-group tiling: each
// block handles 8 rows of one image, loads 9 rows (1.125x traffic).
// ---------------------------------------------------------------------------
__global__ __launch_bounds__(256) void stats_kernel(
    const float* __restrict__ pred, const float* __restrict__ tgt)
{
    __shared__ float sd[2][IMG_W];
    __shared__ float red[8][9];

    const int tid = threadIdx.x;
    const int b   = blockIdx.y;
    const int r0  = blockIdx.x * 8;
    const size_t base = (size_t)b * NPIX;

    float l1 = 0.f, gx = 0.f, gy = 0.f, rng = 0.f;
    float sp = 0.f, st = 0.f, spp = 0.f, stt = 0.f, mse = 0.f;

    for (int rr = 0; rr <= 8; ++rr) {
        const int gr = r0 + rr;
        if (gr < IMG_H) {
            const float4* pr = (const float4*)(pred + base + (size_t)gr * IMG_W);
            const float4* tr = (const float4*)(tgt  + base + (size_t)gr * IMG_W);
            #pragma unroll
            for (int k = 0; k < 2; ++k) {
                const int f = tid + k * 256;           // float4 index, < 512
                const float4 p = pr[f];
                const float4 t = tr[f];
                const float d0 = p.x - t.x, d1 = p.y - t.y;
                const float d2 = p.z - t.z, d3 = p.w - t.w;
                const int c = f * 4;
                sd[rr & 1][c + 0] = d0; sd[rr & 1][c + 1] = d1;
                sd[rr & 1][c + 2] = d2; sd[rr & 1][c + 3] = d3;
                if (rr < 8) {
                    l1 += fabsf(d0) + fabsf(d1) + fabsf(d2) + fabsf(d3);
                    rng += fmaxf(fabsf(p.x) - 1.f, 0.f) + fmaxf(fabsf(p.y) - 1.f, 0.f)
                         + fmaxf(fabsf(p.z) - 1.f, 0.f) + fmaxf(fabsf(p.w) - 1.f, 0.f);
                    sp += p.x + p.y + p.z + p.w;
                    st += t.x + t.y + t.z + t.w;
                    spp = fmaf(p.x, p.x, spp); spp = fmaf(p.y, p.y, spp);
                    spp = fmaf(p.z, p.z, spp); spp = fmaf(p.w, p.w, spp);
                    stt = fmaf(t.x, t.x, stt); stt = fmaf(t.y, t.y, stt);
                    stt = fmaf(t.z, t.z, stt); stt = fmaf(t.w, t.w, stt);
                    float q;
                    q = quant_u8(p.x) - quant_u8(t.x); mse = fmaf(q, q, mse);
                    q = quant_u8(p.y) - quant_u8(t.y); mse = fmaf(q, q, mse);
                    q = quant_u8(p.z) - quant_u8(t.z); mse = fmaf(q, q, mse);
                    q = quant_u8(p.w) - quant_u8(t.w); mse = fmaf(q, q, mse);
                }
            }
        }
        __syncthreads();
        if (rr >= 1 && gr < IMG_H) {                    // pair (gr-1, gr)
            #pragma unroll
            for (int k = 0; k < 8; ++k) {
                const int c = tid + k * 256;
                gx += fabsf(sd[(rr - 1) & 1][c] - sd[rr & 1][c]);
            }
        }
        if (rr < 8) {                                   // gy for self row gr
            const int cur = rr & 1;
            #pragma unroll
            for (int k = 0; k < 8; ++k) {
                const int c = tid + k * 256;
                if (c < IMG_W - 1) gy += fabsf(sd[cur][c] - sd[cur][c + 1]);
            }
        }
        __syncthreads();
    }

    // block reduce 9 values
    float vals[9] = { l1, gx, gy, rng, sp, st, spp, stt, mse };
    const int lane = tid & 31, warp = tid >> 5;
    #pragma unroll
    for (int i = 0; i < 9; ++i) {
        float v = vals[i];
        #pragma unroll
        for (int o = 16; o; o >>= 1) v += __shfl_down_sync(0xffffffffu, v, o);
        if (lane == 0) red[warp][i] = v;
    }
    __syncthreads();
    if (warp == 0 && lane < 9) {
        double s = 0.0;
        #pragma unroll
        for (int w2 = 0; w2 < 8; ++w2) s += (double)red[w2][lane];
        int slot;
        if (lane < 4) slot = lane;                      // l1, gx, gy, range
        else slot = 4 * lane + b - 12;                  // lane 4->4+b ... lane 8->20+b
        atomicAdd(&g_acc[slot], s);
    }
}

// ---------------------------------------------------------------------------
// SSIM kernel: fused quantize + separable 11x11 gaussian conv of the 5 fields
// (p, t, p^2, t^2, p*t) + SSIM map + reduction. 32x32 output tile per block,
// 42x42 input halo in smem, horizontal then vertical pass in smem.
// ---------------------------------------------------------------------------
__global__ __launch_bounds__(256, 2) void ssim_kernel(
    const float* __restrict__ pred, const float* __restrict__ tgt)
{
    __shared__ float  sP[42 * 44];      // stride 44 -> 16B-aligned rows
    __shared__ float  sT[42 * 44];
    __shared__ float4 h4[42 * 32];      // (hp, ht, hpp, htt)
    __shared__ float  h1[42 * 32];      // hpt
    __shared__ float  redsum[8];

    const int tid = threadIdx.x;
    const int x0 = blockIdx.x * 32;
    const int y0 = blockIdx.y * 32;
    const int b  = blockIdx.z;
    const size_t base = (size_t)b * NPIX;

    // ---- load + quantize halo
    for (int i = tid; i < 42 * 42; i += 256) {
        const int r = i / 42, c = i - r * 42;
        const int gy_ = y0 + r, gx_ = x0 + c;
        float p = 0.f, t = 0.f;
        if (gy_ < IMG_H && gx_ < IMG_W) {
            p = pred[base + (size_t)gy_ * IMG_W + gx_];
            t = tgt [base + (size_t)gy_ * IMG_W + gx_];
        }
        sP[r * 44 + c] = quant_u8(p);
        sT[r * 44 + c] = quant_u8(t);
    }
    __syncthreads();

    // ---- horizontal pass: 42 rows x 8 groups of 4 outputs
    for (int it = tid; it < 336; it += 256) {
        const int r = it >> 3, g = it & 7;
        const float4* rp = (const float4*)&sP[r * 44];
        const float4* rt = (const float4*)&sT[r * 44];
        float pv[16], tv[16];
        #pragma unroll
        for (int q = 0; q < 4; ++q) {
            const float4 v = rp[g + q];
            pv[4*q] = v.x; pv[4*q+1] = v.y; pv[4*q+2] = v.z; pv[4*q+3] = v.w;
            const float4 u = rt[g + q];
            tv[4*q] = u.x; tv[4*q+1] = u.y; tv[4*q+2] = u.z; tv[4*q+3] = u.w;
        }
        float pp[14], tt[14], pt[14];
        #pragma unroll
        for (int m = 0; m < 14; ++m) {
            pp[m] = pv[m] * pv[m]; tt[m] = tv[m] * tv[m]; pt[m] = pv[m] * tv[m];
        }
        float hp[4]  = {0,0,0,0}, ht[4]  = {0,0,0,0};
        float hpp[4] = {0,0,0,0}, htt[4] = {0,0,0,0}, hpt[4] = {0,0,0,0};
        const float GWA[11] = { GW0, GW1, GW2, GW3, GW4, GW5, GW4, GW3, GW2, GW1, GW0 };
        #pragma unroll
        for (int j = 0; j < 11; ++j) {
            const float w = GWA[j];
            #pragma unroll
            for (int o = 0; o < 4; ++o) {
                hp [o] = fmaf(w, pv[o + j], hp [o]);
                ht [o] = fmaf(w, tv[o + j], ht [o]);
                hpp[o] = fmaf(w, pp[o + j], hpp[o]);
                htt[o] = fmaf(w, tt[o + j], htt[o]);
                hpt[o] = fmaf(w, pt[o + j], hpt[o]);
            }
        }
        const int oi = r * 32 + 4 * g;
        #pragma unroll
        for (int o = 0; o < 4; ++o) {
            h4[oi + o] = make_float4(hp[o], ht[o], hpp[o], htt[o]);
            h1[oi + o] = hpt[o];
        }
    }
    __syncthreads();

    // ---- vertical pass + ssim: each thread owns a 4-tall output strip
    float ssim_acc = 0.f;
    {
        const int x  = tid & 31;
        const int yb = (tid >> 5) * 4;
        float mu1[4] = {0,0,0,0}, mu2[4] = {0,0,0,0};
        float s11[4] = {0,0,0,0}, s22[4] = {0,0,0,0}, s12[4] = {0,0,0,0};
        const float GWA[11] = { GW0, GW1, GW2, GW3, GW4, GW5, GW4, GW3, GW2, GW1, GW0 };
        #pragma unroll
        for (int r14 = 0; r14 < 14; ++r14) {
            const float4 v  = h4[(yb + r14) * 32 + x];
            const float  w1 = h1[(yb + r14) * 32 + x];
            #pragma unroll
            for (int o = 0; o < 4; ++o) {
                const int j = r14 - o;
                if (j >= 0 && j < 11) {
                    const float w = GWA[j];
                    mu1[o] = fmaf(w, v.x, mu1[o]);
                    mu2[o] = fmaf(w, v.y, mu2[o]);
                    s11[o] = fmaf(w, v.z, s11[o]);
                    s22[o] = fmaf(w, v.w, s22[o]);
                    s12[o] = fmaf(w, w1,  s12[o]);
                }
            }
        }
        #pragma unroll
        for (int o = 0; o < 4; ++o) {
            const int oy = y0 + yb + o, ox = x0 + x;
            if (oy < OUTHW && ox < OUTHW) {
                const float m1 = mu1[o], m2 = mu2[o];
                const float m1s = m1 * m1, m2s = m2 * m2, m12 = m1 * m2;
                const float sig1  = s11[o] - m1s;
                const float sig2  = s22[o] - m2s;
                const float sig12 = s12[o] - m12;
                const float num = (2.f * m12 + C1V) * (2.f * sig12 + C2V);
                const float den = (m1s + m2s + C1V) * (sig1 + sig2 + C2V);
                ssim_acc += num / den;
            }
        }
    }

    // ---- block reduce + atomic
    const int lane = tid & 31, warp = tid >> 5;
    #pragma unroll
    for (int o = 16; o; o >>= 1) ssim_acc += __shfl_down_sync(0xffffffffu, ssim_acc, o);
    if (lane == 0) redsum[warp] = ssim_acc;
    __syncthreads();
    if (warp == 0) {
        float v = (lane < 8) ? redsum[lane] : 0.f;
        #pragma unroll
        for (int o = 4; o; o >>= 1) v += __shfl_down_sync(0xffffffffu, v, o);
        if (lane == 0) {
            const int slot = 32 + ((blockIdx.x + blockIdx.y + blockIdx.z) & 15);
            atomicAdd(&g_acc[slot], (double)v);
        }
    }
}

// ---------------------------------------------------------------------------
__global__ void finalize_kernel(float* __restrict__ out)
{
    const double n = (double)NPIX;
    const double l1 = g_acc[0] / (4.0 * n);
    const double gcnt = 4.0 * 2047.0 * 2048.0;
    const double grad = g_acc[1] / gcnt + g_acc[2] / gcnt;
    const double rng = g_acc[3] / (4.0 * n);

    double energy = 0.0, dist = 0.0, psnr = 0.0;
    for (int b = 0; b < 4; ++b) {
        const double sp  = g_acc[4  + b], st  = g_acc[8  + b];
        const double spp = g_acc[12 + b], stt = g_acc[16 + b];
        const double pm = sp / n, tm = st / n;
        energy += (pm - tm) * (pm - tm);
        const double vp = (spp - sp * sp / n) / (n - 1.0);
        const double vt = (stt - st * st / n) / (n - 1.0);
        const double ps = sqrt(fmax(vp, 0.0));
        const double ts = sqrt(fmax(vt, 0.0));
        dist += (ps - ts) * (ps - ts);
        const double mse = g_acc[20 + b] / n;
        psnr += (mse == 0.0) ? 100.0 : 10.0 * log10(65025.0 / mse);
    }
    energy *= 0.25; dist *= 0.25; psnr *= 0.25;
    const double phys = energy + 0.5 * dist + 0.1 * rng;

    double ss = 0.0;
    for (int i = 32; i < 48; ++i) ss += g_acc[i];
    double ssim_mean = ss / (4.0 * (double)OUTHW * (double)OUTHW);
    ssim_mean = fmin(fmax(ssim_mean, 0.0), 1.0);

    const double total = 1.0 * l1 + 0.15 * grad + 0.05 * phys + 0.1 * (1.0 - ssim_mean);
    out[0] = (float)total;
    out[1] = (float)psnr;
    out[2] = (float)ssim_mean;
}

// ---------------------------------------------------------------------------
extern "C" void kernel_launch(void* const* d_in, const int* in_sizes, int n_in,
                              void* d_out, int out_size)
{
    const float* pred = (const float*)d_in[0];
    const float* tgt  = (const float*)d_in[1];
    float* out = (float*)d_out;

    zero_kernel<<<1, 64>>>();
    {
        dim3 g(IMG_H / 8, NIMG);
        stats_kernel<<<g, 256>>>(pred, tgt);
    }
    {
        dim3 g((OUTHW + 31) / 32, (OUTHW + 31) / 32, NIMG);
        ssim_kernel<<<g, 256>>>(pred, tgt);
    }
    finalize_kernel<<<1, 1>>>(out);
}

// round 2
// speedup vs baseline: 1.1394x; 1.1394x over previous
#include <cuda_runtime.h>
#include <math.h>

#define IMG_H 2048
#define IMG_W 2048
#define NIMG  4
#define NPIX  (IMG_H * IMG_W)
#define OUTHW 2038                 /* 2048 - 11 + 1 */

#define C1V 6.5025f
#define C2V 58.5225f

// Gaussian(11, sigma=1.5) taps (f64-computed, rounded to f32)
#define GW0 0.00102838f
#define GW1 0.00759876f
#define GW2 0.03600077f
#define GW3 0.10936068f
#define GW4 0.21300553f
#define GW5 0.26601172f

#define SP_STRIDE 49   /* 49 mod 32 = 17: conflict-free for 4-row x 8-group warps */
#define H_STRIDE  33   /* 33 mod 32 = 1 : conflict-free h-array access            */

// accumulator slots (doubles), all hashed to avoid single-address atomic serialization:
//   [0..15]   l1      [16..31] gx      [32..47] gy     [48..63] range
//   [64..95]  sum_p[b][h8]   [96..127] sum_t   [128..159] sumsq_p
//   [160..191] sumsq_t      [192..223] mse8    [224..255] ssim
__device__ double g_acc[256];

__device__ __forceinline__ float quant_u8(float x) {
    // identical f32 op sequence to the reference _to_uint8_float
    x = fminf(fmaxf(x, -1.0f), 1.0f);
    float x01 = (x + 1.0f) * 0.5f;
    x01 = fminf(fmaxf(x01, 0.0f), 1.0f);
    float v = x01 * 255.0f;
    v = fminf(v, 255.0f);
    return floorf(v);
}

__global__ void zero_kernel() {
    g_acc[threadIdx.x] = 0.0;
}

// ---------------------------------------------------------------------------
// Fused kernel: per 32x32 output tile —
//   phase 0: load 42x44 halo (float4 LDG), quantize, pointwise stats on the
//            owned 32x32 interior, stash d = p - t for gradients
//   phase 1: gradient stats from smem
//   phase 2: horizontal 11-tap pass over 5 fields (p, t, p^2, t^2, pt)
//   phase 3: vertical 11-tap pass + SSIM map + reduce
// ---------------------------------------------------------------------------
__global__ __launch_bounds__(256, 3) void main_kernel(
    const float* __restrict__ pred, const float* __restrict__ tgt)
{
    __shared__ float sP[42 * SP_STRIDE];
    __shared__ float sT[42 * SP_STRIDE];
    __shared__ float hP [42 * H_STRIDE];
    __shared__ float hT [42 * H_STRIDE];
    __shared__ float hPP[42 * H_STRIDE];
    __shared__ float hTT[42 * H_STRIDE];
    __shared__ float hPT[42 * H_STRIDE];
    __shared__ float red[8][10];
    float* sD = hP;  // alias: d-values live in hP before the horizontal pass (33x33 region)

    const int tid = threadIdx.x;
    const int x0 = blockIdx.x * 32;
    const int y0 = blockIdx.y * 32;
    const int b  = blockIdx.z;
    const size_t base = (size_t)b * NPIX;

    float a_l1 = 0.f, a_gx = 0.f, a_gy = 0.f, a_rng = 0.f;
    float a_sp = 0.f, a_st = 0.f, a_spp = 0.f, a_stt = 0.f, a_mse = 0.f;

    // ---- phase 0: load + quantize + pointwise stats. 42 rows x 11 quads (cols 0..43)
    for (int i = tid; i < 42 * 11; i += 256) {
        const int r = i / 11, q = i - r * 11;
        const int gy_ = y0 + r;
        const int cb  = x0 + 4 * q;
        float4 p4 = make_float4(0.f, 0.f, 0.f, 0.f);
        float4 t4 = make_float4(0.f, 0.f, 0.f, 0.f);
        if (gy_ < IMG_H && cb < IMG_W) {   // width mult of 4 -> quad fully in or out
            const size_t off = base + (size_t)gy_ * IMG_W + cb;
            p4 = *(const float4*)(pred + off);
            t4 = *(const float4*)(tgt  + off);
        }
        const float pe[4] = { p4.x, p4.y, p4.z, p4.w };
        const float te[4] = { t4.x, t4.y, t4.z, t4.w };
        const bool own = (r < 32) && (q < 8);
        #pragma unroll
        for (int e = 0; e < 4; ++e) {
            const float p = pe[e], t = te[e];
            const float qp = quant_u8(p), qt = quant_u8(t);
            const int c = 4 * q + e;
            sP[r * SP_STRIDE + c] = qp;
            sT[r * SP_STRIDE + c] = qt;
            const float d = p - t;
            if (r < 33 && c < 33) sD[r * 33 + c] = d;
            if (own) {
                a_l1  += fabsf(d);
                a_rng += fmaxf(fabsf(p) - 1.f, 0.f);
                a_sp  += p;  a_st += t;
                a_spp = fmaf(p, p, a_spp);
                a_stt = fmaf(t, t, a_stt);
                const float qd = qp - qt;
                a_mse = fmaf(qd, qd, a_mse);
            }
        }
    }
    __syncthreads();

    // ---- phase 1: gradient stats on the owned interior
    for (int i = tid; i < 1024; i += 256) {
        const int r = i >> 5, c = i & 31;
        const float d = sD[r * 33 + c];
        if (y0 + r < IMG_H - 1) a_gx += fabsf(d - sD[(r + 1) * 33 + c]);
        if (x0 + c < IMG_W - 1) a_gy += fabsf(d - sD[r * 33 + c + 1]);
    }
    __syncthreads();

    // ---- phase 2: horizontal pass, 42 rows x 8 groups of 4 outputs
    {
        const float GWA[11] = { GW0, GW1, GW2, GW3, GW4, GW5, GW4, GW3, GW2, GW1, GW0 };
        for (int it = tid; it < 336; it += 256) {
            const int r = it >> 3, g = it & 7;
            const float* rp = &sP[r * SP_STRIDE + g * 4];
            const float* rt = &sT[r * SP_STRIDE + g * 4];
            float pv[14], tv[14];
            #pragma unroll
            for (int m = 0; m < 14; ++m) { pv[m] = rp[m]; tv[m] = rt[m]; }
            float hp[4]  = {0,0,0,0}, ht_[4] = {0,0,0,0};
            float hpp[4] = {0,0,0,0}, htt[4] = {0,0,0,0}, hpt[4] = {0,0,0,0};
            #pragma unroll
            for (int j = 0; j < 11; ++j) {
                const float w = GWA[j];
                #pragma unroll
                for (int o = 0; o < 4; ++o) {
                    const float v = pv[o + j], u = tv[o + j];
                    const float wv = w * v, wu = w * u;
                    hp [o] += wv;  ht_[o] += wu;
                    hpp[o] = fmaf(wv, v, hpp[o]);
                    htt[o] = fmaf(wu, u, htt[o]);
                    hpt[o] = fmaf(wv, u, hpt[o]);
                }
            }
            const int oi = r * H_STRIDE + g * 4;
            #pragma unroll
            for (int o = 0; o < 4; ++o) {
                hP [oi + o] = hp [o];
                hT [oi + o] = ht_[o];
                hPP[oi + o] = hpp[o];
                hTT[oi + o] = htt[o];
                hPT[oi + o] = hpt[o];
            }
        }
    }
    __syncthreads();

    // ---- phase 3: vertical pass + SSIM; each thread owns a 4-tall strip
    float a_ssim = 0.f;
    {
        const float GWA[11] = { GW0, GW1, GW2, GW3, GW4, GW5, GW4, GW3, GW2, GW1, GW0 };
        const int x  = tid & 31;
        const int yb = (tid >> 5) * 4;
        float mu1[4] = {0,0,0,0}, mu2[4] = {0,0,0,0};
        float s11[4] = {0,0,0,0}, s22[4] = {0,0,0,0}, s12[4] = {0,0,0,0};
        #pragma unroll
        for (int r14 = 0; r14 < 14; ++r14) {
            const int row = (yb + r14) * H_STRIDE + x;
            const float va = hP [row];
            const float vb = hT [row];
            const float vc = hPP[row];
            const float vd = hTT[row];
            const float ve = hPT[row];
            #pragma unroll
            for (int o = 0; o < 4; ++o) {
                const int j = r14 - o;
                if (j >= 0 && j < 11) {
                    const float w = GWA[j];
                    mu1[o] = fmaf(w, va, mu1[o]);
                    mu2[o] = fmaf(w, vb, mu2[o]);
                    s11[o] = fmaf(w, vc, s11[o]);
                    s22[o] = fmaf(w, vd, s22[o]);
                    s12[o] = fmaf(w, ve, s12[o]);
                }
            }
        }
        #pragma unroll
        for (int o = 0; o < 4; ++o) {
            const int oy = y0 + yb + o, ox = x0 + x;
            if (oy < OUTHW && ox < OUTHW) {
                const float m1 = mu1[o], m2 = mu2[o];
                const float m1s = m1 * m1, m2s = m2 * m2, m12 = m1 * m2;
                const float sig1  = s11[o] - m1s;
                const float sig2  = s22[o] - m2s;
                const float sig12 = s12[o] - m12;
                const float num = (2.f * m12 + C1V) * (2.f * sig12 + C2V);
                const float den = (m1s + m2s + C1V) * (sig1 + sig2 + C2V);
                a_ssim += num / den;
            }
        }
    }

    // ---- reduce 10 partials, atomics to hashed slots
    float vals[10] = { a_l1, a_gx, a_gy, a_rng, a_sp, a_st, a_spp, a_stt, a_mse, a_ssim };
    const int lane = tid & 31, warp = tid >> 5;
    #pragma unroll
    for (int i = 0; i < 10; ++i) {
        float v = vals[i];
        #pragma unroll
        for (int o = 16; o; o >>= 1) v += __shfl_down_sync(0xffffffffu, v, o);
        if (lane == 0) red[warp][i] = v;
    }
    __syncthreads();
    if (warp == 0 && lane < 10) {
        double s = 0.0;
        #pragma unroll
        for (int w2 = 0; w2 < 8; ++w2) s += (double)red[w2][lane];
        const int h16 = (blockIdx.x + blockIdx.y) & 15;
        const int h8  = (blockIdx.x + blockIdx.y) & 7;
        int slot;
        if (lane < 4) slot = lane * 16 + h16;
        else          slot = 64 + (lane - 4) * 32 + b * 8 + h8;
        atomicAdd(&g_acc[slot], s);
    }
}

// ---------------------------------------------------------------------------
// Finalize: 256 threads gang-load g_acc into smem (parallel MLP), lane 0
// computes the scalars from smem (29-cyc LDS instead of 577-cyc serial LDG).
// ---------------------------------------------------------------------------
__global__ __launch_bounds__(256) void finalize_kernel(float* __restrict__ out)
{
    __shared__ double s[256];
    const int t = threadIdx.x;
    s[t] = g_acc[t];
    __syncthreads();
    if (t == 0) {
        double l1 = 0.0, gxs = 0.0, gys = 0.0, rng = 0.0;
        for (int i = 0; i < 16; ++i) {
            l1 += s[i]; gxs += s[16 + i]; gys += s[32 + i]; rng += s[48 + i];
        }
        const double n = (double)NPIX;
        l1  /= 4.0 * n;
        rng /= 4.0 * n;
        const double gcnt = 4.0 * 2047.0 * 2048.0;
        const double grad = gxs / gcnt + gys / gcnt;

        double energy = 0.0, dist = 0.0, psnr = 0.0;
        for (int bb = 0; bb < 4; ++bb) {
            double sp = 0, st = 0, spp = 0, stt = 0, mse = 0;
            for (int h = 0; h < 8; ++h) {
                sp  += s[64  + bb * 8 + h];
                st  += s[96  + bb * 8 + h];
                spp += s[128 + bb * 8 + h];
                stt += s[160 + bb * 8 + h];
                mse += s[192 + bb * 8 + h];
            }
            const double pm = sp / n, tm = st / n;
            energy += (pm - tm) * (pm - tm);
            const double vp = (spp - sp * sp / n) / (n - 1.0);
            const double vt = (stt - st * st / n) / (n - 1.0);
            const double ps = sqrt(fmax(vp, 0.0));
            const double ts = sqrt(fmax(vt, 0.0));
            dist += (ps - ts) * (ps - ts);
            mse /= n;
            psnr += (mse == 0.0) ? 100.0 : 10.0 * log10(65025.0 / mse);
        }
        energy *= 0.25; dist *= 0.25; psnr *= 0.25;
        const double phys = energy + 0.5 * dist + 0.1 * rng;

        double ss = 0.0;
        for (int i = 224; i < 256; ++i) ss += s[i];
        double ssim_mean = ss / (4.0 * (double)OUTHW * (double)OUTHW);
        ssim_mean = fmin(fmax(ssim_mean, 0.0), 1.0);

        const double total = l1 + 0.15 * grad + 0.05 * phys + 0.1 * (1.0 - ssim_mean);
        out[0] = (float)total;
        out[1] = (float)psnr;
        out[2] = (float)ssim_mean;
    }
}

// ---------------------------------------------------------------------------
extern "C" void kernel_launch(void* const* d_in, const int* in_sizes, int n_in,
                              void* d_out, int out_size)
{
    const float* pred = (const float*)d_in[0];
    const float* tgt  = (const float*)d_in[1];
    float* out = (float*)d_out;

    zero_kernel<<<1, 256>>>();
    {
        dim3 g((OUTHW + 31) / 32, (OUTHW + 31) / 32, NIMG);
        main_kernel<<<g, 256>>>(pred, tgt);
    }
    finalize_kernel<<<1, 256>>>(out);
}

// round 3
// speedup vs baseline: 1.4556x; 1.2775x over previous
#include <cuda_runtime.h>
#include <math.h>

#define IMG_H 2048
#define IMG_W 2048
#define NIMG  4
#define NPIX  (IMG_H * IMG_W)
#define OUTHW 2038                 /* 2048 - 11 + 1 */

#define C1V 6.5025f
#define C2V 58.5225f

#define TILE_W 32
#define TILE_H 64
#define HALO_H (TILE_H + 10)       /* 74 */
#define SP_STRIDE 49               /* 49 mod 32 = 17 -> conflict-free */
#define H_STRIDE  33

/* dynamic smem layout (floats) */
#define OFF_SP 0
#define OFF_ST (HALO_H * SP_STRIDE)                    /* 3626  */
#define OFF_HP (2 * HALO_H * SP_STRIDE)                /* 7252  */
#define OFF_HT (OFF_HP + HALO_H * H_STRIDE)            /* 9694  */
#define OFF_HS (OFF_HT + HALO_H * H_STRIDE)            /* 12136 */
#define OFF_HQ (OFF_HS + HALO_H * H_STRIDE)            /* 14578 */
#define SMEM_FLOATS (OFF_HQ + HALO_H * H_STRIDE)       /* 17020 */
#define SMEM_BYTES  (SMEM_FLOATS * 4)                  /* 68080 */

// accumulator slots (doubles), hashed:
//   [0..15] l1  [16..31] gx  [32..47] gy  [48..63] range
//   [64..95] sum_p[b][h8]  [96..127] sum_t  [128..159] sumsq_p
//   [160..191] sumsq_t  [192..223] mse8  [224..255] ssim
__device__ double g_acc[256];

__device__ __forceinline__ float quant_u8(float x) {
    // bitwise-identical to reference clip chain for all finite x
    return floorf(__saturatef((x + 1.0f) * 0.5f) * 255.0f);
}

// ---------------------------------------------------------------------------
__global__ __launch_bounds__(256, 3) void main_kernel(
    const float* __restrict__ pred, const float* __restrict__ tgt)
{
    extern __shared__ float sm[];
    float* sP = sm + OFF_SP;
    float* sT = sm + OFF_ST;
    float* hP = sm + OFF_HP;
    float* hT = sm + OFF_HT;
    float* hS = sm + OFF_HS;
    float* hQ = sm + OFF_HQ;
    float* sD = hP;                       // alias: 65x33 d-values before h-pass
    __shared__ float red[8][10];

    const int tid = threadIdx.x;
    const int x0 = blockIdx.x * TILE_W;
    const int y0 = blockIdx.y * TILE_H;
    const int b  = blockIdx.z;
    const size_t base = (size_t)b * NPIX;

    float a_l1 = 0.f, a_gx = 0.f, a_gy = 0.f, a_rng = 0.f;
    float a_sp = 0.f, a_st = 0.f, a_spp = 0.f, a_stt = 0.f, a_mse = 0.f;

    // ---- phase 0: load halo (74 rows x 11 quads), quantize, pointwise stats
    for (int i = tid; i < HALO_H * 11; i += 256) {
        const int r = i / 11, q = i - r * 11;
        const int gy_ = y0 + r;
        const int cb  = x0 + 4 * q;
        float4 p4 = make_float4(0.f, 0.f, 0.f, 0.f);
        float4 t4 = make_float4(0.f, 0.f, 0.f, 0.f);
        if (gy_ < IMG_H && cb < IMG_W) {
            const size_t off = base + (size_t)gy_ * IMG_W + cb;
            p4 = *(const float4*)(pred + off);
            t4 = *(const float4*)(tgt  + off);
        }
        const float pe[4] = { p4.x, p4.y, p4.z, p4.w };
        const float te[4] = { t4.x, t4.y, t4.z, t4.w };
        const bool own = (r < TILE_H) && (q < 8);
        #pragma unroll
        for (int e = 0; e < 4; ++e) {
            const float p = pe[e], t = te[e];
            const float qp = quant_u8(p), qt = quant_u8(t);
            const int c = 4 * q + e;
            sP[r * SP_STRIDE + c] = qp;
            sT[r * SP_STRIDE + c] = qt;
            const float d = p - t;
            if (r < TILE_H + 1 && c < TILE_W + 1) sD[r * 33 + c] = d;
            if (own) {
                a_l1  += fabsf(d);
                a_rng += fmaxf(fabsf(p) - 1.f, 0.f);
                a_sp  += p;  a_st += t;
                a_spp = fmaf(p, p, a_spp);
                a_stt = fmaf(t, t, a_stt);
                const float qd = qp - qt;
                a_mse = fmaf(qd, qd, a_mse);
            }
        }
    }
    __syncthreads();

    // ---- phase 1: gradient stats on the owned interior (64x32)
    for (int i = tid; i < TILE_H * TILE_W; i += 256) {
        const int r = i >> 5, c = i & 31;
        const float d = sD[r * 33 + c];
        if (y0 + r < IMG_H - 1) a_gx += fabsf(d - sD[(r + 1) * 33 + c]);
        if (x0 + c < IMG_W - 1) a_gy += fabsf(d - sD[r * 33 + c + 1]);
    }
    __syncthreads();

    // ---- phase 2: horizontal 11-tap pass, element loop -> pure FFMA-imm
    {
        const float GWA[11] = { 0.00102838f, 0.00759876f, 0.03600077f, 0.10936068f,
                                0.21300553f, 0.26601172f, 0.21300553f, 0.10936068f,
                                0.03600077f, 0.00759876f, 0.00102838f };
        for (int it = tid; it < HALO_H * 8; it += 256) {
            const int r = it >> 3, g = it & 7;
            const float* rp = &sP[r * SP_STRIDE + 4 * g];
            const float* rt = &sT[r * SP_STRIDE + 4 * g];
            float hp[4] = {0,0,0,0}, ht_[4] = {0,0,0,0};
            float hs[4] = {0,0,0,0}, hq[4]  = {0,0,0,0};
            #pragma unroll
            for (int m = 0; m < 14; ++m) {
                const float p = rp[m], t = rt[m];
                const float s = fmaf(p, p, t * t);
                const float q = p * t;
                #pragma unroll
                for (int o = 0; o < 4; ++o) {
                    const int j = m - o;
                    if (j >= 0 && j < 11) {
                        const float w = GWA[j];
                        hp [o] = fmaf(w, p, hp [o]);
                        ht_[o] = fmaf(w, t, ht_[o]);
                        hs [o] = fmaf(w, s, hs [o]);
                        hq [o] = fmaf(w, q, hq [o]);
                    }
                }
            }
            const int oi = r * H_STRIDE + 4 * g;
            #pragma unroll
            for (int o = 0; o < 4; ++o) {
                hP[oi + o] = hp [o];
                hT[oi + o] = ht_[o];
                hS[oi + o] = hs [o];
                hQ[oi + o] = hq [o];
            }
        }
    }
    __syncthreads();

    // ---- phase 3: vertical pass + SSIM; each thread owns an 8-tall strip
    float a_ssim = 0.f;
    {
        const float GWA[11] = { 0.00102838f, 0.00759876f, 0.03600077f, 0.10936068f,
                                0.21300553f, 0.26601172f, 0.21300553f, 0.10936068f,
                                0.03600077f, 0.00759876f, 0.00102838f };
        const int x  = tid & 31;
        const int yb = (tid >> 5) * 8;
        float mu1[8], mu2[8], ss_[8], sq_[8];
        #pragma unroll
        for (int o = 0; o < 8; ++o) { mu1[o] = mu2[o] = ss_[o] = sq_[o] = 0.f; }
        #pragma unroll
        for (int rr = 0; rr < 18; ++rr) {
            const int row = (yb + rr) * H_STRIDE + x;
            const float va = hP[row];
            const float vb = hT[row];
            const float vc = hS[row];
            const float vd = hQ[row];
            #pragma unroll
            for (int o = 0; o < 8; ++o) {
                const int j = rr - o;
                if (j >= 0 && j < 11) {
                    const float w = GWA[j];
                    mu1[o] = fmaf(w, va, mu1[o]);
                    mu2[o] = fmaf(w, vb, mu2[o]);
                    ss_[o] = fmaf(w, vc, ss_[o]);
                    sq_[o] = fmaf(w, vd, sq_[o]);
                }
            }
        }
        #pragma unroll
        for (int o = 0; o < 8; ++o) {
            const int oy = y0 + yb + o, ox = x0 + x;
            if (oy < OUTHW && ox < OUTHW) {
                const float m1 = mu1[o], m2 = mu2[o];
                const float m1s = m1 * m1, m2s = m2 * m2, m12 = m1 * m2;
                const float sigsum = ss_[o] - m1s - m2s;   // sigma1 + sigma2
                const float sig12  = sq_[o] - m12;
                const float num = (2.f * m12 + C1V) * (2.f * sig12 + C2V);
                const float den = (m1s + m2s + C1V) * (sigsum + C2V);
                a_ssim += __fdividef(num, den);
            }
        }
    }

    // ---- reduce 10 partials, atomics to hashed slots
    float vals[10] = { a_l1, a_gx, a_gy, a_rng, a_sp, a_st, a_spp, a_stt, a_mse, a_ssim };
    const int lane = tid & 31, warp = tid >> 5;
    #pragma unroll
    for (int i = 0; i < 10; ++i) {
        float v = vals[i];
        #pragma unroll
        for (int o = 16; o; o >>= 1) v += __shfl_down_sync(0xffffffffu, v, o);
        if (lane == 0) red[warp][i] = v;
    }
    __syncthreads();
    if (warp == 0 && lane < 10) {
        double s = 0.0;
        #pragma unroll
        for (int w2 = 0; w2 < 8; ++w2) s += (double)red[w2][lane];
        const int h16 = (blockIdx.x + blockIdx.y) & 15;
        const int h8  = (blockIdx.x + blockIdx.y) & 7;
        int slot;
        if (lane < 4) slot = lane * 16 + h16;
        else          slot = 64 + (lane - 4) * 32 + b * 8 + h8;
        atomicAdd(&g_acc[slot], s);
    }
}

// ---------------------------------------------------------------------------
// Finalize: gang-load g_acc -> smem, zero g_acc for the next launch (module
// load zero-inits it for the first), lane 0 computes scalars from smem.
// ---------------------------------------------------------------------------
__global__ __launch_bounds__(256) void finalize_kernel(float* __restrict__ out)
{
    __shared__ double s[256];
    const int t = threadIdx.x;
    s[t] = g_acc[t];
    __syncthreads();
    g_acc[t] = 0.0;
    if (t == 0) {
        double l1 = 0.0, gxs = 0.0, gys = 0.0, rng = 0.0;
        for (int i = 0; i < 16; ++i) {
            l1 += s[i]; gxs += s[16 + i]; gys += s[32 + i]; rng += s[48 + i];
        }
        const double n = (double)NPIX;
        l1  /= 4.0 * n;
        rng /= 4.0 * n;
        const double gcnt = 4.0 * 2047.0 * 2048.0;
        const double grad = gxs / gcnt + gys / gcnt;

        double energy = 0.0, dist = 0.0, psnr = 0.0;
        for (int bb = 0; bb < 4; ++bb) {
            double sp = 0, st = 0, spp = 0, stt = 0, mse = 0;
            for (int h = 0; h < 8; ++h) {
                sp  += s[64  + bb * 8 + h];
                st  += s[96  + bb * 8 + h];
                spp += s[128 + bb * 8 + h];
                stt += s[160 + bb * 8 + h];
                mse += s[192 + bb * 8 + h];
            }
            const double pm = sp / n, tm = st / n;
            energy += (pm - tm) * (pm - tm);
            const double vp = (spp - sp * sp / n) / (n - 1.0);
            const double vt = (stt - st * st / n) / (n - 1.0);
            const double ps = sqrt(fmax(vp, 0.0));
            const double ts = sqrt(fmax(vt, 0.0));
            dist += (ps - ts) * (ps - ts);
            mse /= n;
            psnr += (mse == 0.0) ? 100.0 : 10.0 * log10(65025.0 / mse);
        }
        energy *= 0.25; dist *= 0.25; psnr *= 0.25;
        const double phys = energy + 0.5 * dist + 0.1 * rng;

        double ss = 0.0;
        for (int i = 224; i < 256; ++i) ss += s[i];
        double ssim_mean = ss / (4.0 * (double)OUTHW * (double)OUTHW);
        ssim_mean = fmin(fmax(ssim_mean, 0.0), 1.0);

        const double total = l1 + 0.15 * grad + 0.05 * phys + 0.1 * (1.0 - ssim_mean);
        out[0] = (float)total;
        out[1] = (float)psnr;
        out[2] = (float)ssim_mean;
    }
}

// ---------------------------------------------------------------------------
extern "C" void kernel_launch(void* const* d_in, const int* in_sizes, int n_in,
                              void* d_out, int out_size)
{
    const float* pred = (const float*)d_in[0];
    const float* tgt  = (const float*)d_in[1];
    float* out = (float*)d_out;

    cudaFuncSetAttribute(main_kernel,
                         cudaFuncAttributeMaxDynamicSharedMemorySize, SMEM_BYTES);
    {
        dim3 g(IMG_W / TILE_W, IMG_H / TILE_H, NIMG);   // 64 x 32 x 4
        main_kernel<<<g, 256, SMEM_BYTES>>>(pred, tgt);
    }
    finalize_kernel<<<1, 256>>>(out);
}

// round 4
// speedup vs baseline: 1.9047x; 1.3085x over previous
#include <cuda_runtime.h>
#include <cuda_fp16.h>
#include <math.h>

#define IMG_H 2048
#define IMG_W 2048
#define NIMG  4
#define NPIX  (IMG_H * IMG_W)
#define OUTHW 2038                 /* 2048 - 11 + 1 */

#define C1V 6.5025f
#define C2V 58.5225f

#define TILE_W 32
#define TILE_H 64
#define HALO_H (TILE_H + 10)       /* 74 */
#define SP_STRIDE 49               /* half2 units; 49 mod 32 = 17 -> conflict-free */
#define H_STRIDE  33               /* ull units */

typedef unsigned long long ull;

/* dynamic smem layout (bytes) */
#define OFF_SPT 0                                    /* half2[74*49]  = 14504 B */
#define OFF_HPT 14504                                /* ull  [74*33]  = 19536 B */
#define OFF_HSQ (14504 + 19536)                      /* ull  [74*33]  = 19536 B */
#define SMEM_BYTES (OFF_HSQ + 19536)                 /* 53576 B -> 4 blocks/SM  */

#define PACKF2(out, lo, hi) \
    asm("mov.b64 %0, {%1, %2};" : "=l"(out) : "f"(lo), "f"(hi))
#define UNPACKF2(lo, hi, in) \
    asm("mov.b64 {%0, %1}, %2;" : "=f"(lo), "=f"(hi) : "l"(in))
#define FMA2(d, a, b, c) \
    asm("fma.rn.f32x2 %0, %1, %2, %3;" : "=l"(d) : "l"(a), "l"(b), "l"(c))
#define ADD2(d, a, b) \
    asm("add.rn.f32x2 %0, %1, %2;" : "=l"(d) : "l"(a), "l"(b))

// accumulator slots (doubles), hashed:
//   [0..15] l1  [16..31] gx  [32..47] gy  [48..63] range
//   [64..95] sum_p[b][h8]  [96..127] sum_t  [128..159] sumsq_p
//   [160..191] sumsq_t  [192..223] mse8  [224..255] ssim
__device__ double g_acc[256];

__device__ __forceinline__ float quant_u8(float x) {
    return floorf(__saturatef((x + 1.0f) * 0.5f) * 255.0f);
}

// ---------------------------------------------------------------------------
__global__ __launch_bounds__(256, 4) void main_kernel(
    const float* __restrict__ pred, const float* __restrict__ tgt)
{
    extern __shared__ unsigned char smraw[];
    __half2* sPT = (__half2*)(smraw + OFF_SPT);
    ull*     hPT = (ull*)(smraw + OFF_HPT);
    ull*     hSQ = (ull*)(smraw + OFF_HSQ);
    float*   sD  = (float*)(smraw + OFF_HSQ);   // alias, dead before hSQ written
    __shared__ ull  redu[8][5];
    __shared__ float redf[8];

    const int tid = threadIdx.x;
    const int lane = tid & 31, warp = tid >> 5;
    const int x0 = blockIdx.x * TILE_W;
    const int y0 = blockIdx.y * TILE_H;
    const int b  = blockIdx.z;
    const size_t base = (size_t)b * NPIX;
    const int h16 = (blockIdx.x + blockIdx.y) & 15;
    const int h8  = (blockIdx.x + blockIdx.y) & 7;

    // packed tap weights (symmetric: 6 distinct)
    const float GW[6] = { 0.00102838f, 0.00759876f, 0.03600077f,
                          0.10936068f, 0.21300553f, 0.26601172f };
    ull W2[6];
    #pragma unroll
    for (int j = 0; j < 6; ++j) PACKF2(W2[j], GW[j], GW[j]);

    float a_l1 = 0.f, a_gx = 0.f, a_gy = 0.f, a_rng = 0.f;
    float a_sp = 0.f, a_st = 0.f, a_spp = 0.f, a_stt = 0.f, a_mse = 0.f;

    // ---- phase 0: load halo, quantize, pointwise stats
    for (int i = tid; i < HALO_H * 11; i += 256) {
        const int r = i / 11, q = i - r * 11;
        const int gy_ = y0 + r;
        const int cb  = x0 + 4 * q;
        float4 p4 = make_float4(0.f, 0.f, 0.f, 0.f);
        float4 t4 = make_float4(0.f, 0.f, 0.f, 0.f);
        if (gy_ < IMG_H && cb < IMG_W) {
            const size_t off = base + (size_t)gy_ * IMG_W + cb;
            p4 = *(const float4*)(pred + off);
            t4 = *(const float4*)(tgt  + off);
        }
        const float pe[4] = { p4.x, p4.y, p4.z, p4.w };
        const float te[4] = { t4.x, t4.y, t4.z, t4.w };
        const bool own = (r < TILE_H) && (q < 8);
        #pragma unroll
        for (int e = 0; e < 4; ++e) {
            const float p = pe[e], t = te[e];
            const float qp = quant_u8(p), qt = quant_u8(t);
            const int c = 4 * q + e;
            sPT[r * SP_STRIDE + c] = __floats2half2_rn(qp, qt);
            const float d = p - t;
            if (r < TILE_H + 1 && c < TILE_W + 1) sD[r * 33 + c] = d;
            if (own) {
                a_l1  += fabsf(d);
                a_rng += fmaxf(fabsf(p) - 1.f, 0.f);
                a_sp  += p;  a_st += t;
                a_spp = fmaf(p, p, a_spp);
                a_stt = fmaf(t, t, a_stt);
                const float qd = qp - qt;
                a_mse = fmaf(qd, qd, a_mse);
            }
        }
    }
    __syncthreads();

    // ---- phase 1: gradient stats on the owned interior (64x32)
    for (int i = tid; i < TILE_H * TILE_W; i += 256) {
        const int r = i >> 5, c = i & 31;
        const float d = sD[r * 33 + c];
        if (y0 + r < IMG_H - 1) a_gx += fabsf(d - sD[(r + 1) * 33 + c]);
        if (x0 + c < IMG_W - 1) a_gy += fabsf(d - sD[r * 33 + c + 1]);
    }

    // ---- flush the 9 pointwise stats now (frees registers for conv phases)
    {
        ull v[5];
        PACKF2(v[0], a_l1, a_gx);
        PACKF2(v[1], a_gy, a_rng);
        PACKF2(v[2], a_sp, a_st);
        PACKF2(v[3], a_spp, a_stt);
        PACKF2(v[4], a_mse, 0.f);
        #pragma unroll
        for (int i = 0; i < 5; ++i) {
            #pragma unroll
            for (int o = 16; o; o >>= 1) {
                ull t2 = __shfl_down_sync(0xffffffffu, v[i], o);
                ADD2(v[i], v[i], t2);
            }
            if (lane == 0) redu[warp][i] = v[i];
        }
    }
    __syncthreads();
    if (warp == 0 && lane < 5) {
        ull s2 = redu[0][lane];
        #pragma unroll
        for (int w2 = 1; w2 < 8; ++w2) ADD2(s2, s2, redu[w2][lane]);
        float va, vb; UNPACKF2(va, vb, s2);
        int sa, sb;
        switch (lane) {
            case 0: sa = 0 + h16;               sb = 16 + h16;              break;
            case 1: sa = 32 + h16;              sb = 48 + h16;              break;
            case 2: sa = 64 + b * 8 + h8;       sb = 96 + b * 8 + h8;       break;
            case 3: sa = 128 + b * 8 + h8;      sb = 160 + b * 8 + h8;      break;
            default: sa = 192 + b * 8 + h8;     sb = -1;                    break;
        }
        atomicAdd(&g_acc[sa], (double)va);
        if (sb >= 0) atomicAdd(&g_acc[sb], (double)vb);
    }
    __syncthreads();   // sD dead; hPT/hSQ may now be written

    // ---- phase 2: horizontal 11-tap pass, paired fields via fma.f32x2
    for (int it = tid; it < HALO_H * 4; it += 256) {
        const int r = it % HALO_H;        // r-major lanes -> conflict-free STS.64
        const int g = it / HALO_H;        // 0..3, 8 outputs each
        const __half2* row = &sPT[r * SP_STRIDE + 8 * g];
        ull accPT[8], accSQ[8];
        #pragma unroll
        for (int o = 0; o < 8; ++o) { accPT[o] = 0ull; accSQ[o] = 0ull; }
        #pragma unroll
        for (int m = 0; m < 18; ++m) {
            const float2 f = __half22float2(row[m]);
            ull pt2; PACKF2(pt2, f.x, f.y);
            const float q = f.x * f.y;
            const float s_ = fmaf(f.x, f.x, f.y * f.y);
            ull sq2; PACKF2(sq2, s_, q);
            #pragma unroll
            for (int o = 0; o < 8; ++o) {
                const int j = m - o;
                if (j >= 0 && j < 11) {
                    const int wi = (j < 6) ? j : 10 - j;
                    FMA2(accPT[o], W2[wi], pt2, accPT[o]);
                    FMA2(accSQ[o], W2[wi], sq2, accSQ[o]);
                }
            }
        }
        const int oi = r * H_STRIDE + 8 * g;
        #pragma unroll
        for (int o = 0; o < 8; ++o) {
            hPT[oi + o] = accPT[o];
            hSQ[oi + o] = accSQ[o];
        }
    }
    __syncthreads();

    // ---- phase 3: vertical pass + SSIM; each thread owns an 8-tall strip
    float a_ssim = 0.f;
    {
        const int x  = lane;
        const int yb = warp * 8;
        ull accM[8], accS[8];
        #pragma unroll
        for (int o = 0; o < 8; ++o) { accM[o] = 0ull; accS[o] = 0ull; }
        #pragma unroll
        for (int rr = 0; rr < 18; ++rr) {
            const int row = (yb + rr) * H_STRIDE + x;
            const ull vpt = hPT[row];
            const ull vsq = hSQ[row];
            #pragma unroll
            for (int o = 0; o < 8; ++o) {
                const int j = rr - o;
                if (j >= 0 && j < 11) {
                    const int wi = (j < 6) ? j : 10 - j;
                    FMA2(accM[o], W2[wi], vpt, accM[o]);
                    FMA2(accS[o], W2[wi], vsq, accS[o]);
                }
            }
        }
        #pragma unroll
        for (int o = 0; o < 8; ++o) {
            const int oy = y0 + yb + o, ox = x0 + x;
            if (oy < OUTHW && ox < OUTHW) {
                float m1, m2, css, csq;
                UNPACKF2(m1, m2, accM[o]);
                UNPACKF2(css, csq, accS[o]);
                const float m1s = m1 * m1, m2s = m2 * m2, m12 = m1 * m2;
                const float sigsum = css - m1s - m2s;     // sigma1 + sigma2
                const float sig12  = csq - m12;
                const float num = (2.f * m12 + C1V) * (2.f * sig12 + C2V);
                const float den = (m1s + m2s + C1V) * (sigsum + C2V);
                a_ssim += __fdividef(num, den);
            }
        }
    }

    // ---- ssim reduction
    #pragma unroll
    for (int o = 16; o; o >>= 1) a_ssim += __shfl_down_sync(0xffffffffu, a_ssim, o);
    if (lane == 0) redf[warp] = a_ssim;
    __syncthreads();
    if (warp == 0) {
        float v = (lane < 8) ? redf[lane] : 0.f;
        #pragma unroll
        for (int o = 4; o; o >>= 1) v += __shfl_down_sync(0xffffffffu, v, o);
        if (lane == 0)
            atomicAdd(&g_acc[224 + ((blockIdx.x + blockIdx.y) & 31)], (double)v);
    }
}

// ---------------------------------------------------------------------------
// Parallel finalize: group sums in 32 lanes, per-image sqrt/log10 in 4 lanes,
// thread 0 combines. g_acc re-zeroed for the next replay.
// ---------------------------------------------------------------------------
__global__ __launch_bounds__(256) void finalize_kernel(float* __restrict__ out)
{
    __shared__ double s[256];
    __shared__ double g2[32];
    __shared__ double per[12];
    const int t = threadIdx.x;
    s[t] = g_acc[t];
    __syncthreads();
    g_acc[t] = 0.0;

    if (t < 32) {
        const int base = (t < 24) ? (64 + 8 * t) : (8 * (t - 24));
        double v = 0.0;
        #pragma unroll
        for (int i = 0; i < 8; ++i) v += s[base + i];
        g2[t] = v;
    }
    __syncthreads();

    const double n = (double)NPIX;
    if (t < 4) {   // per-image stats in parallel
        const double sp  = g2[t],      st  = g2[4 + t];
        const double spp = g2[8 + t],  stt = g2[12 + t];
        const double mse = g2[16 + t] / n;
        const double pm = sp / n, tm = st / n;
        per[t] = (pm - tm) * (pm - tm);
        const double vp = (spp - sp * sp / n) / (n - 1.0);
        const double vt = (stt - st * st / n) / (n - 1.0);
        const double ps = sqrt(fmax(vp, 0.0));
        const double ts = sqrt(fmax(vt, 0.0));
        per[4 + t] = (ps - ts) * (ps - ts);
        per[8 + t] = (mse == 0.0) ? 100.0 : 10.0 * log10(65025.0 / mse);
    }
    __syncthreads();

    if (t == 0) {
        const double l1  = (g2[24] + g2[25]) / (4.0 * n);
        const double gcnt = 4.0 * 2047.0 * 2048.0;
        const double grad = (g2[26] + g2[27]) / gcnt + (g2[28] + g2[29]) / gcnt;
        const double rng = (g2[30] + g2[31]) / (4.0 * n);

        const double energy = 0.25 * (per[0] + per[1] + per[2] + per[3]);
        const double dist   = 0.25 * (per[4] + per[5] + per[6] + per[7]);
        const double psnr   = 0.25 * (per[8] + per[9] + per[10] + per[11]);
        const double phys = energy + 0.5 * dist + 0.1 * rng;

        const double ss = g2[20] + g2[21] + g2[22] + g2[23];
        double ssim_mean = ss / (4.0 * (double)OUTHW * (double)OUTHW);
        ssim_mean = fmin(fmax(ssim_mean, 0.0), 1.0);

        const double total = l1 + 0.15 * grad + 0.05 * phys + 0.1 * (1.0 - ssim_mean);
        out[0] = (float)total;
        out[1] = (float)psnr;
        out[2] = (float)ssim_mean;
    }
}

// ---------------------------------------------------------------------------
extern "C" void kernel_launch(void* const* d_in, const int* in_sizes, int n_in,
                              void* d_out, int out_size)
{
    const float* pred = (const float*)d_in[0];
    const float* tgt  = (const float*)d_in[1];
    float* out = (float*)d_out;

    cudaFuncSetAttribute(main_kernel,
                         cudaFuncAttributeMaxDynamicSharedMemorySize, SMEM_BYTES);
    {
        dim3 g(IMG_W / TILE_W, IMG_H / TILE_H, NIMG);   // 64 x 32 x 4
        main_kernel<<<g, 256, SMEM_BYTES>>>(pred, tgt);
    }
    finalize_kernel<<<1, 256>>>(out);
}